// round 2
// baseline (speedup 1.0000x reference)
#include <cuda_runtime.h>
#include <cstdint>

// Problem constants
#define BATCH 8
#define NNODE 2048
#define NEDGE 65536
#define HDIM  128
#define NRAD  6
#define TILE_E 128

typedef unsigned long long u64;

// Precomputed params (device globals — no allocation)
__device__ float g_u1[HDIM];
__device__ float g_u2[HDIM];
__device__ float g_c[HDIM];
__device__ float g_W3t[HDIM * HDIM];   // [k][o] = lin_w[o, 256+k]

// ---------------------------------------------------------------------------
// Precompute u1 = W1 @ emb_w, u2 = W2 @ emb_w, c = (W1+W2) @ emb_b + lin_b
// ---------------------------------------------------------------------------
__global__ void precompute_uc(const float* __restrict__ emb_w,
                              const float* __restrict__ emb_b,
                              const float* __restrict__ lin_w,
                              const float* __restrict__ lin_b) {
    int o = threadIdx.x;   // 0..127
    float u1 = 0.f, u2 = 0.f, cc = 0.f;
    const float* row = lin_w + o * (3 * HDIM);
    #pragma unroll 4
    for (int h = 0; h < HDIM; ++h) {
        float w1 = row[h];
        float w2 = row[HDIM + h];
        float ew = emb_w[h];
        float eb = emb_b[h];
        u1 = fmaf(w1, ew, u1);
        u2 = fmaf(w2, ew, u2);
        cc = fmaf(w1 + w2, eb, cc);
    }
    g_u1[o] = u1;
    g_u2[o] = u2;
    g_c[o]  = cc + lin_b[o];
}

// Transpose W3 = lin_w[:, 256:384] into k-major layout
__global__ void precompute_w3t(const float* __restrict__ lin_w) {
    int idx = blockIdx.x * blockDim.x + threadIdx.x;  // 0..16383
    int k = idx >> 7;
    int o = idx & 127;
    g_W3t[k * HDIM + o] = lin_w[o * (3 * HDIM) + 2 * HDIM + k];
}

// ---------------------------------------------------------------------------
// Packed f32x2 helpers (ptxas will not auto-fuse FFMA2 from C++)
// ---------------------------------------------------------------------------
__device__ __forceinline__ u64 pack2(float lo, float hi) {
    u64 r;
    asm("mov.b64 %0, {%1, %2};" : "=l"(r) : "f"(lo), "f"(hi));
    return r;
}
__device__ __forceinline__ void fma2(u64& d, u64 a, u64 b) {
    asm("fma.rn.f32x2 %0, %1, %2, %0;" : "+l"(d) : "l"(a), "l"(b));
}
__device__ __forceinline__ float lo2(u64 v) { return __uint_as_float((unsigned)v); }
__device__ __forceinline__ float hi2(u64 v) { return __uint_as_float((unsigned)(v >> 32)); }

__device__ __forceinline__ float fast_silu(float z) {
    // z * sigmoid(z); __expf -> MUFU ex2, __fdividef -> MUFU rcp. ~1e-6 rel err.
    return __fdividef(z, 1.0f + __expf(-z));
}

// ---------------------------------------------------------------------------
// Main fused kernel. One CTA = 128 edges x 128 output channels of one batch.
// smem: W3t (k-major) 64KB, r-tile (k-major) 64KB, small staging buffers.
// ---------------------------------------------------------------------------
#define SMEM_FLOATS (16384 /*W3t*/ + 16384 /*r*/ + 768 /*rbfT*/ + 768 /*rw*/ + 128 /*rb*/ + 128 /*xi*/ + 128 /*xj*/)
#define SMEM_BYTES  (SMEM_FLOATS * 4)

__global__ void __launch_bounds__(256, 1)
edge_mlp_kernel(const float* __restrict__ x,
                const float* __restrict__ rbf,
                const int* __restrict__ iidx,
                const int* __restrict__ jidx,
                const float* __restrict__ rbf_w,
                const float* __restrict__ rbf_b,
                float* __restrict__ out) {
    extern __shared__ float sm[];
    float* W3t  = sm;                 // [128][128] k-major
    float* r_s  = sm + 16384;         // [128][128] k-major: r_s[k*128+e]
    float* rbfT = r_s + 16384;        // [6][128]
    float* rwm  = rbfT + 768;         // [128][6] raw copy of rbf_w
    float* rb_s = rwm + 768;          // [128]
    float* xi_s = rb_s + 128;         // [128]
    float* xj_s = xi_s + 128;         // [128]

    const int b   = blockIdx.y;
    const int e0  = blockIdx.x * TILE_E;
    const int tid = threadIdx.x;

    // ---- stage W3t (coalesced, conflict-free: already transposed in gmem) ----
    {
        const float4* src = (const float4*)g_W3t;
        float4* dst = (float4*)W3t;
        #pragma unroll
        for (int it = 0; it < 16; ++it)
            dst[tid + it * 256] = src[tid + it * 256];
    }
    // ---- stage rbf tile transposed: rbfT[m][e] ----
    {
        const float* rbf_base = rbf + ((size_t)b * NEDGE + e0) * NRAD;
        #pragma unroll
        for (int it = 0; it < 3; ++it) {
            int idx = tid + it * 256;   // 0..767
            float v = rbf_base[idx];
            int e = idx / NRAD, m = idx % NRAD;
            rbfT[m * 128 + e] = v;
        }
    }
    // ---- stage rbf_w / rbf_b ----
    {
        #pragma unroll
        for (int it = 0; it < 3; ++it)
            rwm[tid + it * 256] = rbf_w[tid + it * 256];
        if (tid < 128) rb_s[tid] = rbf_b[tid];
    }
    // ---- gather x_i, x_j for this edge tile ----
    // NOTE: indices are int32 on device (JAX x64 disabled demotes int64->int32).
    // Mask with NNODE-1 so a bad index can never fault (only mis-read).
    if (tid < 128) {
        int e = e0 + tid;
        int ii = iidx[e] & (NNODE - 1);
        int jj = jidx[e] & (NNODE - 1);
        xi_s[tid] = x[b * NNODE + ii];
        xj_s[tid] = x[b * NNODE + jj];
    }
    __syncthreads();

    // ---- compute r tile: r_s[k][e] = silu(rbf_b[k] + sum_m rbfT[m][e]*rbf_w[k][m]) ----
    {
        const int e  = tid & 127;
        const int k0 = tid >> 7;   // 0 or 1
        float rm[NRAD];
        #pragma unroll
        for (int m = 0; m < NRAD; ++m) rm[m] = rbfT[m * 128 + e];
        #pragma unroll 4
        for (int k = k0; k < 128; k += 2) {
            float z = rb_s[k];
            #pragma unroll
            for (int m = 0; m < NRAD; ++m)
                z = fmaf(rm[m], rwm[k * NRAD + m], z);
            r_s[k * 128 + e] = fast_silu(z);
        }
    }
    __syncthreads();

    // ---- main contraction: s[e][o] = sum_k r[e][k] * W3[o][k] ----
    // thread tile: 8 edges (as 4 packed pairs) x 8 outputs (oc..oc+3, 64+oc..64+oc+3)
    const int c      = tid & 15;     // output-quad group
    const int eg     = tid >> 4;     // edge group 0..15
    const int e_base = eg * 8;
    const int oc     = c * 4;

    u64 acc[4][8];
    #pragma unroll
    for (int ep = 0; ep < 4; ++ep)
        #pragma unroll
        for (int q = 0; q < 8; ++q)
            acc[ep][q] = 0ull;

    #pragma unroll 2
    for (int k = 0; k < 128; ++k) {
        // r pairs: 128-bit loads give packed (e, e+1) f32x2 for free
        const ulonglong2 rv0 = *(const ulonglong2*)(r_s + k * 128 + e_base);
        const ulonglong2 rv1 = *(const ulonglong2*)(r_s + k * 128 + e_base + 4);
        u64 rp[4] = { rv0.x, rv0.y, rv1.x, rv1.y };

        const float4 w0 = *(const float4*)(W3t + k * 128 + oc);
        const float4 w1 = *(const float4*)(W3t + k * 128 + 64 + oc);
        u64 wd[8];
        wd[0] = pack2(w0.x, w0.x); wd[1] = pack2(w0.y, w0.y);
        wd[2] = pack2(w0.z, w0.z); wd[3] = pack2(w0.w, w0.w);
        wd[4] = pack2(w1.x, w1.x); wd[5] = pack2(w1.y, w1.y);
        wd[6] = pack2(w1.z, w1.z); wd[7] = pack2(w1.w, w1.w);

        #pragma unroll
        for (int ep = 0; ep < 4; ++ep)
            #pragma unroll
            for (int q = 0; q < 8; ++q)
                fma2(acc[ep][q], rp[ep], wd[q]);
    }

    // ---- epilogue: add rank-1 node terms, silu, store ----
    float u1v[8], u2v[8], cv[8];
    #pragma unroll
    for (int q = 0; q < 4; ++q) {
        u1v[q]     = g_u1[oc + q];      u1v[4 + q] = g_u1[64 + oc + q];
        u2v[q]     = g_u2[oc + q];      u2v[4 + q] = g_u2[64 + oc + q];
        cv[q]      = g_c[oc + q];       cv[4 + q]  = g_c[64 + oc + q];
    }

    const size_t out_base = ((size_t)b * NEDGE + e0) * HDIM;
    #pragma unroll
    for (int ep = 0; ep < 4; ++ep) {
        #pragma unroll
        for (int h = 0; h < 2; ++h) {
            const int er = e_base + 2 * ep + h;
            const float xi = xi_s[er];
            const float xj = xj_s[er];
            float res[8];
            #pragma unroll
            for (int q = 0; q < 8; ++q) {
                float s   = h ? hi2(acc[ep][q]) : lo2(acc[ep][q]);
                float pre = s + xi * u1v[q] + xj * u2v[q] + cv[q];
                res[q] = fast_silu(pre);
            }
            float* orow = out + out_base + (size_t)er * HDIM;
            *(float4*)(orow + oc)      = make_float4(res[0], res[1], res[2], res[3]);
            *(float4*)(orow + 64 + oc) = make_float4(res[4], res[5], res[6], res[7]);
        }
    }
}

// ---------------------------------------------------------------------------
extern "C" void kernel_launch(void* const* d_in, const int* in_sizes, int n_in,
                              void* d_out, int out_size) {
    const float* x     = (const float*)d_in[0];
    const float* rbf   = (const float*)d_in[1];
    const int*   iidx  = (const int*)d_in[2];   // int32: JAX demotes int64 (x64 disabled)
    const int*   jidx  = (const int*)d_in[3];
    const float* emb_w = (const float*)d_in[4];
    const float* emb_b = (const float*)d_in[5];
    const float* rbf_w = (const float*)d_in[6];
    const float* rbf_b = (const float*)d_in[7];
    const float* lin_w = (const float*)d_in[8];
    const float* lin_b = (const float*)d_in[9];
    float* out = (float*)d_out;

    precompute_uc<<<1, 128>>>(emb_w, emb_b, lin_w, lin_b);
    precompute_w3t<<<64, 256>>>(lin_w);

    cudaFuncSetAttribute(edge_mlp_kernel,
                         cudaFuncAttributeMaxDynamicSharedMemorySize, SMEM_BYTES);
    dim3 grid(NEDGE / TILE_E, BATCH);   // (512, 8)
    edge_mlp_kernel<<<grid, 256, SMEM_BYTES>>>(x, rbf, iidx, jidx, rbf_w, rbf_b, out);
}

// round 4
// speedup vs baseline: 1.5677x; 1.5677x over previous
#include <cuda_runtime.h>
#include <cuda_bf16.h>
#include <cstdint>

#define BATCH 8
#define NNODE 2048
#define NEDGE 65536
#define HDIM  128
#define NRAD  6
#define TILE_E 128

typedef unsigned long long u64;

// ---------------- device globals (no allocation) ----------------
__device__ float g_u1[HDIM];
__device__ float g_u2[HDIM];
__device__ float g_c[HDIM];
// W3 (lin_w[:,256:384]) as bf16 hi/lo, stored in mma.m16n8k16 A-fragment order:
// index ((tm*8 + tk)*32 + lane) -> uint4 = {a0,a1,a2,a3}
__device__ uint4 g_WA_hi[8 * 8 * 32];
__device__ uint4 g_WA_lo[8 * 8 * 32];

// ---------------- smem byte offsets ----------------
#define OFF_BHI  0        // r hi, B-fragment order: 32768 B
#define OFF_BLO  32768    // r lo: 32768 B
#define OFF_RBF  65536    // rbf tile [128][6] f32: 3072 B
#define OFF_RWT  68608    // rbf_w transposed [6][128] f32: 3072 B
#define OFF_RBB  71680    // rbf_b [128] f32: 512 B
#define OFF_XI   72192    // 512 B
#define OFF_XJ   72704    // 512 B
#define SMEM_BYTES 73216

// ---------------- helpers ----------------
__device__ __forceinline__ uint32_t smem_u32(const void* p) {
    uint32_t a;
    asm("{ .reg .u64 t; cvta.to.shared.u64 t, %1; cvt.u32.u64 %0, t; }" : "=r"(a) : "l"(p));
    return a;
}
__device__ __forceinline__ u64 lds64(uint32_t addr) {
    u64 v;
    asm volatile("ld.shared.b64 %0, [%1];" : "=l"(v) : "r"(addr));
    return v;
}
__device__ __forceinline__ void sts64(uint32_t addr, u64 v) {
    asm volatile("st.shared.b64 [%0], %1;" :: "r"(addr), "l"(v) : "memory");
}
// packed bf16x2: low half = lo, high half = hi
__device__ __forceinline__ uint32_t cvt_bf16x2(float lo, float hi) {
    uint32_t d;
    asm("cvt.rn.bf16x2.f32 %0, %2, %1;" : "=r"(d) : "f"(lo), "f"(hi));
    return d;
}
__device__ __forceinline__ void mma16816(float* d, const uint4& a, u64 b) {
    uint32_t b0 = (uint32_t)b, b1 = (uint32_t)(b >> 32);
    asm volatile(
        "mma.sync.aligned.m16n8k16.row.col.f32.bf16.bf16.f32 "
        "{%0,%1,%2,%3}, {%4,%5,%6,%7}, {%8,%9}, {%0,%1,%2,%3};"
        : "+f"(d[0]), "+f"(d[1]), "+f"(d[2]), "+f"(d[3])
        : "r"(a.x), "r"(a.y), "r"(a.z), "r"(a.w), "r"(b0), "r"(b1));
}
__device__ __forceinline__ float fast_silu(float z) {
    return __fdividef(z, 1.0f + __expf(-z));
}

// ---------------------------------------------------------------------------
// precompute: u1 = W1@emb_w, u2 = W2@emb_w, c = (W1+W2)@emb_b + lin_b
// ---------------------------------------------------------------------------
__global__ void precompute_uc(const float* __restrict__ emb_w,
                              const float* __restrict__ emb_b,
                              const float* __restrict__ lin_w,
                              const float* __restrict__ lin_b) {
    __shared__ float red[3][4];
    const int o = blockIdx.x;
    const int h = threadIdx.x;
    float w1 = lin_w[o * (3 * HDIM) + h];
    float w2 = lin_w[o * (3 * HDIM) + HDIM + h];
    float u1 = w1 * emb_w[h];
    float u2 = w2 * emb_w[h];
    float cc = (w1 + w2) * emb_b[h];
    #pragma unroll
    for (int s = 16; s > 0; s >>= 1) {
        u1 += __shfl_down_sync(0xffffffff, u1, s);
        u2 += __shfl_down_sync(0xffffffff, u2, s);
        cc += __shfl_down_sync(0xffffffff, cc, s);
    }
    if ((h & 31) == 0) { red[0][h >> 5] = u1; red[1][h >> 5] = u2; red[2][h >> 5] = cc; }
    __syncthreads();
    if (h == 0) {
        g_u1[o] = red[0][0] + red[0][1] + red[0][2] + red[0][3];
        g_u2[o] = red[1][0] + red[1][1] + red[1][2] + red[1][3];
        g_c[o]  = red[2][0] + red[2][1] + red[2][2] + red[2][3] + lin_b[o];
    }
}

// precompute W3 hi/lo in A-fragment-packed order.
// A frag (m16n8k16): a0=(o,k0|k1) a1=(o+8,k0|k1) a2=(o,k8|k9) a3=(o+8,k8|k9)
// with o = tm*16 + (lane>>2), k0 = tk*16 + (lane&3)*2.
__global__ void precompute_w3pack(const float* __restrict__ lin_w) {
    int idx = blockIdx.x * blockDim.x + threadIdx.x;   // 0..2047
    int lane = idx & 31;
    int t    = idx >> 5;         // 0..63
    int tk   = t & 7;
    int tm   = t >> 3;
    int o0 = tm * 16 + (lane >> 2);
    int o1 = o0 + 8;
    int k0 = tk * 16 + (lane & 3) * 2;

    float w[2][4];  // [o-half][k: k0,k0+1,k0+8,k0+9]
    #pragma unroll
    for (int kk = 0; kk < 2; ++kk) {
        w[0][kk]     = lin_w[o0 * (3 * HDIM) + 2 * HDIM + k0 + kk];
        w[0][2 + kk] = lin_w[o0 * (3 * HDIM) + 2 * HDIM + k0 + 8 + kk];
        w[1][kk]     = lin_w[o1 * (3 * HDIM) + 2 * HDIM + k0 + kk];
        w[1][2 + kk] = lin_w[o1 * (3 * HDIM) + 2 * HDIM + k0 + 8 + kk];
    }
    uint32_t h[2][2], l[2][2];
    #pragma unroll
    for (int r = 0; r < 2; ++r) {
        #pragma unroll
        for (int pp = 0; pp < 2; ++pp) {
            float f0 = w[r][pp * 2], f1 = w[r][pp * 2 + 1];
            uint32_t hp = cvt_bf16x2(f0, f1);
            float h0 = __uint_as_float(hp << 16);
            float h1 = __uint_as_float(hp & 0xFFFF0000u);
            h[r][pp] = hp;
            l[r][pp] = cvt_bf16x2(f0 - h0, f1 - h1);
        }
    }
    // uint4 = {a0, a1, a2, a3}
    g_WA_hi[idx] = make_uint4(h[0][0], h[1][0], h[0][1], h[1][1]);
    g_WA_lo[idx] = make_uint4(l[0][0], l[1][0], l[0][1], l[1][1]);
}

// ---------------------------------------------------------------------------
// Main fused kernel: 1 CTA = 128 edges x 128 outputs, mma.sync split-bf16
// ---------------------------------------------------------------------------
__global__ void __launch_bounds__(256, 2)
edge_mlp_kernel(const float* __restrict__ x,
                const float* __restrict__ rbf,
                const int* __restrict__ iidx,
                const int* __restrict__ jidx,
                const float* __restrict__ rbf_w,
                const float* __restrict__ rbf_b,
                float* __restrict__ out) {
    extern __shared__ char sm[];
    const uint32_t sb = smem_u32(sm);

    const int b    = blockIdx.y;
    const int e0   = blockIdx.x * TILE_E;
    const int tid  = threadIdx.x;
    const int wid  = tid >> 5;
    const int lane = tid & 31;

    float* rbf_s = (float*)(sm + OFF_RBF);
    float* rwT   = (float*)(sm + OFF_RWT);
    float* rbb   = (float*)(sm + OFF_RBB);
    float* xi_s  = (float*)(sm + OFF_XI);
    float* xj_s  = (float*)(sm + OFF_XJ);

    // ---- stage rbf tile [128][6] ----
    {
        const float* src = rbf + ((size_t)b * NEDGE + e0) * NRAD;
        #pragma unroll
        for (int it = 0; it < 3; ++it)
            rbf_s[tid + it * 256] = src[tid + it * 256];
    }
    // ---- stage rbf_w transposed [m][k] + rbf_b ----
    {
        #pragma unroll
        for (int it = 0; it < 3; ++it) {
            int idx = tid + it * 256;       // 0..767
            int m = idx >> 7, k = idx & 127;
            rwT[m * 128 + k] = rbf_w[k * NRAD + m];
        }
        if (tid < 128) rbb[tid] = rbf_b[tid];
    }
    // ---- gather x_i / x_j (int32 indices; mask so bad index cannot fault) ----
    if (tid < 128) {
        int e = e0 + tid;
        int ii = iidx[e] & (NNODE - 1);
        int jj = jidx[e] & (NNODE - 1);
        xi_s[tid] = x[b * NNODE + ii];
        xj_s[tid] = x[b * NNODE + jj];
    }
    __syncthreads();

    // ---- r tile: silu(rbf @ rbf_w.T + rbf_b), split bf16 hi/lo, written in
    //      B-fragment order: addr ((tn*8+kt)*32 + lane)*8 ----
    // B frag: b0 = r[e = tn*8 + lane>>2][k = kt*16 + (lane&3)*2 + {0,1}]
    //         b1 = same e, k+8  -> one 8B store per (tile, lane).
    {
        #pragma unroll 2
        for (int t = 0; t < 16; ++t) {
            const int tn = wid * 2 + (t >> 3);
            const int kt = t & 7;
            const int e  = tn * 8 + (lane >> 2);
            const int kb = kt * 16 + (lane & 3) * 2;

            float rbv[NRAD];
            #pragma unroll
            for (int m = 0; m < NRAD; ++m) rbv[m] = rbf_s[e * NRAD + m];

            float z0 = rbb[kb], z1 = rbb[kb + 1];
            float z2 = rbb[kb + 8], z3 = rbb[kb + 9];
            #pragma unroll
            for (int m = 0; m < NRAD; ++m) {
                float2 wa = *(const float2*)(rwT + m * 128 + kb);
                float2 wb = *(const float2*)(rwT + m * 128 + kb + 8);
                z0 = fmaf(rbv[m], wa.x, z0);
                z1 = fmaf(rbv[m], wa.y, z1);
                z2 = fmaf(rbv[m], wb.x, z2);
                z3 = fmaf(rbv[m], wb.y, z3);
            }
            float r0 = fast_silu(z0), r1 = fast_silu(z1);
            float r2 = fast_silu(z2), r3 = fast_silu(z3);

            uint32_t h01 = cvt_bf16x2(r0, r1);
            uint32_t h23 = cvt_bf16x2(r2, r3);
            float h0 = __uint_as_float(h01 << 16);
            float h1 = __uint_as_float(h01 & 0xFFFF0000u);
            float h2 = __uint_as_float(h23 << 16);
            float h3 = __uint_as_float(h23 & 0xFFFF0000u);
            uint32_t l01 = cvt_bf16x2(r0 - h0, r1 - h1);
            uint32_t l23 = cvt_bf16x2(r2 - h2, r3 - h3);

            uint32_t off = (uint32_t)(((tn * 8 + kt) * 32 + lane) * 8);
            sts64(sb + OFF_BHI + off, (u64)h01 | ((u64)h23 << 32));
            sts64(sb + OFF_BLO + off, (u64)l01 | ((u64)l23 << 32));
        }
    }
    __syncthreads();

    // ---- mma: D[o][e] = sum_k W[o,k]*r[e,k]; warp tile 32(o) x 64(e) ----
    const int wm = wid & 3;     // o-group: rows wm*32..+31
    const int wn = wid >> 1 & 0; // placeholder (computed below)
    const int wng = wid >> 2;   // e-group: cols wng*64..+63
    (void)wn;

    float acc[2][8][4];
    #pragma unroll
    for (int i = 0; i < 2; ++i)
        #pragma unroll
        for (int j = 0; j < 8; ++j)
            #pragma unroll
            for (int q = 0; q < 4; ++q) acc[i][j][q] = 0.f;

    // 3 passes: (Whi,rhi), (Whi,rlo), (Wlo,rhi)
    #pragma unroll
    for (int term = 0; term < 3; ++term) {
        const uint4* Ap = (term == 2) ? g_WA_lo : g_WA_hi;
        const uint32_t Boff = (term == 1) ? OFF_BLO : OFF_BHI;
        #pragma unroll
        for (int kt = 0; kt < 8; ++kt) {
            uint4 a0 = __ldg(Ap + ((wm * 2 + 0) * 8 + kt) * 32 + lane);
            uint4 a1 = __ldg(Ap + ((wm * 2 + 1) * 8 + kt) * 32 + lane);
            u64 bb[8];
            #pragma unroll
            for (int j = 0; j < 8; ++j)
                bb[j] = lds64(sb + Boff +
                              (uint32_t)((((wng * 8 + j) * 8 + kt) * 32 + lane) * 8));
            #pragma unroll
            for (int j = 0; j < 8; ++j) {
                mma16816(acc[0][j], a0, bb[j]);
                mma16816(acc[1][j], a1, bb[j]);
            }
        }
    }

    // ---- epilogue: pre = acc + xi*u1[o] + xj*u2[o] + c[o]; out = silu(pre) ----
    // D frag: c0=(o, e) c1=(o, e+1) c2=(o+8, e) c3=(o+8, e+1),
    // o = wm*32 + i*16 + lane>>2, e = wng*64 + j*8 + (lane&3)*2
    float u1v[2][2], u2v[2][2], cv[2][2];
    #pragma unroll
    for (int i = 0; i < 2; ++i) {
        int ob = wm * 32 + i * 16 + (lane >> 2);
        u1v[i][0] = __ldg(g_u1 + ob);     u1v[i][1] = __ldg(g_u1 + ob + 8);
        u2v[i][0] = __ldg(g_u2 + ob);     u2v[i][1] = __ldg(g_u2 + ob + 8);
        cv[i][0]  = __ldg(g_c + ob);      cv[i][1]  = __ldg(g_c + ob + 8);
    }

    float* outb = out + ((size_t)b * NEDGE + e0) * HDIM;
    #pragma unroll
    for (int j = 0; j < 8; ++j) {
        const int eb = wng * 64 + j * 8 + (lane & 3) * 2;
        const float2 xiv = *(const float2*)(xi_s + eb);
        const float2 xjv = *(const float2*)(xj_s + eb);
        #pragma unroll
        for (int i = 0; i < 2; ++i) {
            const int ob = wm * 32 + i * 16 + (lane >> 2);
            #pragma unroll
            for (int h = 0; h < 2; ++h) {           // o vs o+8
                float p0 = acc[i][j][h * 2 + 0];
                float p1 = acc[i][j][h * 2 + 1];
                p0 = fmaf(xiv.x, u1v[i][h], p0);
                p0 = fmaf(xjv.x, u2v[i][h], p0) + cv[i][h];
                p1 = fmaf(xiv.y, u1v[i][h], p1);
                p1 = fmaf(xjv.y, u2v[i][h], p1) + cv[i][h];
                const int oo = ob + h * 8;
                outb[(size_t)eb * HDIM + oo]       = fast_silu(p0);
                outb[(size_t)(eb + 1) * HDIM + oo] = fast_silu(p1);
            }
        }
    }
}

// ---------------------------------------------------------------------------
extern "C" void kernel_launch(void* const* d_in, const int* in_sizes, int n_in,
                              void* d_out, int out_size) {
    const float* x     = (const float*)d_in[0];
    const float* rbf   = (const float*)d_in[1];
    const int*   iidx  = (const int*)d_in[2];   // int32 (JAX x64 disabled)
    const int*   jidx  = (const int*)d_in[3];
    const float* emb_w = (const float*)d_in[4];
    const float* emb_b = (const float*)d_in[5];
    const float* rbf_w = (const float*)d_in[6];
    const float* rbf_b = (const float*)d_in[7];
    const float* lin_w = (const float*)d_in[8];
    const float* lin_b = (const float*)d_in[9];
    float* out = (float*)d_out;

    precompute_uc<<<HDIM, 128>>>(emb_w, emb_b, lin_w, lin_b);
    precompute_w3pack<<<8, 256>>>(lin_w);

    cudaFuncSetAttribute(edge_mlp_kernel,
                         cudaFuncAttributeMaxDynamicSharedMemorySize, SMEM_BYTES);
    dim3 grid(NEDGE / TILE_E, BATCH);   // (512, 8)
    edge_mlp_kernel<<<grid, 256, SMEM_BYTES>>>(x, rbf, iidx, jidx, rbf_w, rbf_b, out);
}

// round 5
// speedup vs baseline: 2.8338x; 1.8076x over previous
#include <cuda_runtime.h>
#include <cuda_fp16.h>
#include <cstdint>

#define BATCH 8
#define NNODE 2048
#define NEDGE 65536
#define HDIM  128
#define NRAD  6
#define TILE_E 128

typedef unsigned long long u64;

// ---------------- device globals (no allocation) ----------------
__device__ float g_u1[HDIM];
__device__ float g_u2[HDIM];
__device__ float g_c[HDIM];
// W3 (lin_w[:,256:384]) as fp16 hi/lo, in mma.m16n8k16 A-fragment order:
// index ((tm*8 + tk)*32 + lane) -> uint4 = {a0,a1,a2,a3}
__device__ uint4 g_WA_hi[8 * 8 * 32];
__device__ uint4 g_WA_lo[8 * 8 * 32];

// ---------------- smem byte offsets ----------------
#define OFF_B    0        // r fp16, B-fragment order: 32768 B
#define OFF_RBF  32768    // rbf tile [128][6] f32: 3072 B
#define OFF_RWT  35840    // rbf_w transposed [6][128] f32: 3072 B
#define OFF_RBB  38912    // rbf_b [128] f32: 512 B
#define OFF_XI   39424    // 512 B
#define OFF_XJ   39936    // 512 B
#define SMEM_BYTES 40448

// ---------------- helpers ----------------
__device__ __forceinline__ uint32_t smem_u32(const void* p) {
    uint32_t a;
    asm("{ .reg .u64 t; cvta.to.shared.u64 t, %1; cvt.u32.u64 %0, t; }" : "=r"(a) : "l"(p));
    return a;
}
__device__ __forceinline__ u64 lds64(uint32_t addr) {
    u64 v;
    asm volatile("ld.shared.b64 %0, [%1];" : "=l"(v) : "r"(addr));
    return v;
}
__device__ __forceinline__ void sts64(uint32_t addr, u64 v) {
    asm volatile("st.shared.b64 [%0], %1;" :: "r"(addr), "l"(v) : "memory");
}
// packed f16x2: low half <- lo, high half <- hi
__device__ __forceinline__ uint32_t cvt_f16x2(float lo, float hi) {
    uint32_t d;
    asm("cvt.rn.f16x2.f32 %0, %2, %1;" : "=r"(d) : "f"(lo), "f"(hi));
    return d;
}
__device__ __forceinline__ void mma16816(float* d, const uint4& a, u64 b) {
    uint32_t b0 = (uint32_t)b, b1 = (uint32_t)(b >> 32);
    asm volatile(
        "mma.sync.aligned.m16n8k16.row.col.f32.f16.f16.f32 "
        "{%0,%1,%2,%3}, {%4,%5,%6,%7}, {%8,%9}, {%0,%1,%2,%3};"
        : "+f"(d[0]), "+f"(d[1]), "+f"(d[2]), "+f"(d[3])
        : "r"(a.x), "r"(a.y), "r"(a.z), "r"(a.w), "r"(b0), "r"(b1));
}
__device__ __forceinline__ float fast_silu(float z) {
    return __fdividef(z, 1.0f + __expf(-z));
}

// ---------------------------------------------------------------------------
// Single precompute kernel (keeps launch count at 2 per replay so ncu -s 5
// lands on the main kernel).
// grid=64, block=256.
//   part A: u1/u2/c for o = bid*2 + (tid>>7)   (128-length dot, 4-warp reduce)
//   part B: blocks 0..7 pack W3 hi/lo fp16 A-fragments (2048 threads)
// ---------------------------------------------------------------------------
__global__ void precompute_all(const float* __restrict__ emb_w,
                               const float* __restrict__ emb_b,
                               const float* __restrict__ lin_w,
                               const float* __restrict__ lin_b) {
    __shared__ float red[2][3][4];
    const int tid = threadIdx.x;
    const int bid = blockIdx.x;

    // ---- part A ----
    {
        const int half = tid >> 7;            // which o of this block
        const int o = bid * 2 + half;
        const int h = tid & 127;
        float w1 = lin_w[o * (3 * HDIM) + h];
        float w2 = lin_w[o * (3 * HDIM) + HDIM + h];
        float u1 = w1 * emb_w[h];
        float u2 = w2 * emb_w[h];
        float cc = (w1 + w2) * emb_b[h];
        #pragma unroll
        for (int s = 16; s > 0; s >>= 1) {
            u1 += __shfl_down_sync(0xffffffff, u1, s);
            u2 += __shfl_down_sync(0xffffffff, u2, s);
            cc += __shfl_down_sync(0xffffffff, cc, s);
        }
        const int w4 = (tid >> 5) & 3;
        if ((tid & 31) == 0) {
            red[half][0][w4] = u1; red[half][1][w4] = u2; red[half][2][w4] = cc;
        }
        __syncthreads();
        if ((tid & 127) == 0) {
            g_u1[o] = red[half][0][0] + red[half][0][1] + red[half][0][2] + red[half][0][3];
            g_u2[o] = red[half][1][0] + red[half][1][1] + red[half][1][2] + red[half][1][3];
            g_c[o]  = red[half][2][0] + red[half][2][1] + red[half][2][2] + red[half][2][3]
                      + lin_b[o];
        }
    }

    // ---- part B: W3 fp16 hi/lo A-fragment pack ----
    // A frag (m16n8k16): a0=(o,k0|k1) a1=(o+8,k0|k1) a2=(o,k8|k9) a3=(o+8,k8|k9)
    // o = tm*16 + (lane>>2), k0 = tk*16 + (lane&3)*2.
    const int idx = bid * 256 + tid;
    if (idx < 2048) {
        const int lane = idx & 31;
        const int t    = idx >> 5;      // 0..63
        const int tk   = t & 7;
        const int tm   = t >> 3;
        const int o0 = tm * 16 + (lane >> 2);
        const int o1 = o0 + 8;
        const int k0 = tk * 16 + (lane & 3) * 2;

        float w[2][4];  // [o-half][k: k0,k0+1,k0+8,k0+9]
        #pragma unroll
        for (int kk = 0; kk < 2; ++kk) {
            w[0][kk]     = lin_w[o0 * (3 * HDIM) + 2 * HDIM + k0 + kk];
            w[0][2 + kk] = lin_w[o0 * (3 * HDIM) + 2 * HDIM + k0 + 8 + kk];
            w[1][kk]     = lin_w[o1 * (3 * HDIM) + 2 * HDIM + k0 + kk];
            w[1][2 + kk] = lin_w[o1 * (3 * HDIM) + 2 * HDIM + k0 + 8 + kk];
        }
        uint32_t hp[2][2], lp[2][2];
        #pragma unroll
        for (int r = 0; r < 2; ++r) {
            #pragma unroll
            for (int pp = 0; pp < 2; ++pp) {
                float f0 = w[r][pp * 2], f1 = w[r][pp * 2 + 1];
                __half h0 = __float2half_rn(f0);
                __half h1 = __float2half_rn(f1);
                float  r0 = f0 - __half2float(h0);
                float  r1 = f1 - __half2float(h1);
                hp[r][pp] = cvt_f16x2(__half2float(h0), __half2float(h1));
                lp[r][pp] = cvt_f16x2(r0, r1);
            }
        }
        g_WA_hi[idx] = make_uint4(hp[0][0], hp[1][0], hp[0][1], hp[1][1]);
        g_WA_lo[idx] = make_uint4(lp[0][0], lp[1][0], lp[0][1], lp[1][1]);
    }
}

// ---------------------------------------------------------------------------
// Main fused kernel: 1 CTA = 128 edges x 128 outputs, mma.sync fp16 2-term
//   D[o][e] = (Whi + Wlo) @ r[e]^T ,  r in single fp16 (err ~2^-11, averages)
// ---------------------------------------------------------------------------
__global__ void __launch_bounds__(256, 2)
edge_mlp_kernel(const float* __restrict__ x,
                const float* __restrict__ rbf,
                const int* __restrict__ iidx,
                const int* __restrict__ jidx,
                const float* __restrict__ rbf_w,
                const float* __restrict__ rbf_b,
                float* __restrict__ out) {
    extern __shared__ char sm[];
    const uint32_t sb = smem_u32(sm);

    const int b    = blockIdx.y;
    const int e0   = blockIdx.x * TILE_E;
    const int tid  = threadIdx.x;
    const int wid  = tid >> 5;
    const int lane = tid & 31;

    float* rbf_s = (float*)(sm + OFF_RBF);
    float* rwT   = (float*)(sm + OFF_RWT);
    float* rbb   = (float*)(sm + OFF_RBB);
    float* xi_s  = (float*)(sm + OFF_XI);
    float* xj_s  = (float*)(sm + OFF_XJ);

    // ---- stage rbf tile [128][6] ----
    {
        const float* src = rbf + ((size_t)b * NEDGE + e0) * NRAD;
        #pragma unroll
        for (int it = 0; it < 3; ++it)
            rbf_s[tid + it * 256] = src[tid + it * 256];
    }
    // ---- stage rbf_w transposed [m][k] + rbf_b ----
    {
        #pragma unroll
        for (int it = 0; it < 3; ++it) {
            int idx = tid + it * 256;       // 0..767
            int m = idx >> 7, k = idx & 127;
            rwT[m * 128 + k] = rbf_w[k * NRAD + m];
        }
        if (tid < 128) rbb[tid] = rbf_b[tid];
    }
    // ---- gather x_i / x_j (int32 indices; mask so bad index cannot fault) ----
    if (tid < 128) {
        int e = e0 + tid;
        int ii = iidx[e] & (NNODE - 1);
        int jj = jidx[e] & (NNODE - 1);
        xi_s[tid] = x[b * NNODE + ii];
        xj_s[tid] = x[b * NNODE + jj];
    }
    __syncthreads();

    // ---- r tile: silu(rbf @ rbf_w.T + rbf_b) -> fp16, B-fragment order ----
    // B frag element: b0 = r[e][k0,k0+1], b1 = r[e][k0+8,k0+9],
    // e = tn*8 + lane>>2, k0 = kt*16 + (lane&3)*2; addr ((tn*8+kt)*32+lane)*8
    {
        #pragma unroll 2
        for (int t = 0; t < 16; ++t) {
            const int tn = wid * 2 + (t >> 3);
            const int kt = t & 7;
            const int e  = tn * 8 + (lane >> 2);
            const int kb = kt * 16 + (lane & 3) * 2;

            float rbv[NRAD];
            #pragma unroll
            for (int m = 0; m < NRAD; ++m) rbv[m] = rbf_s[e * NRAD + m];

            float z0 = rbb[kb], z1 = rbb[kb + 1];
            float z2 = rbb[kb + 8], z3 = rbb[kb + 9];
            #pragma unroll
            for (int m = 0; m < NRAD; ++m) {
                float2 wa = *(const float2*)(rwT + m * 128 + kb);
                float2 wb = *(const float2*)(rwT + m * 128 + kb + 8);
                z0 = fmaf(rbv[m], wa.x, z0);
                z1 = fmaf(rbv[m], wa.y, z1);
                z2 = fmaf(rbv[m], wb.x, z2);
                z3 = fmaf(rbv[m], wb.y, z3);
            }
            uint32_t b01 = cvt_f16x2(fast_silu(z0), fast_silu(z1));
            uint32_t b23 = cvt_f16x2(fast_silu(z2), fast_silu(z3));

            uint32_t off = (uint32_t)(((tn * 8 + kt) * 32 + lane) * 8);
            sts64(sb + OFF_B + off, (u64)b01 | ((u64)b23 << 32));
        }
    }
    __syncthreads();

    // ---- mma: warp tile 32(o) x 64(e); 2 terms share the B fragments ----
    const int wm  = wid & 3;    // o-group: rows wm*32..+31
    const int wng = wid >> 2;   // e-group: cols wng*64..+63

    float acc[2][8][4];
    #pragma unroll
    for (int i = 0; i < 2; ++i)
        #pragma unroll
        for (int j = 0; j < 8; ++j)
            #pragma unroll
            for (int q = 0; q < 4; ++q) acc[i][j][q] = 0.f;

    #pragma unroll
    for (int kt = 0; kt < 8; ++kt) {
        uint4 a0h = __ldg(g_WA_hi + ((wm * 2 + 0) * 8 + kt) * 32 + lane);
        uint4 a1h = __ldg(g_WA_hi + ((wm * 2 + 1) * 8 + kt) * 32 + lane);
        uint4 a0l = __ldg(g_WA_lo + ((wm * 2 + 0) * 8 + kt) * 32 + lane);
        uint4 a1l = __ldg(g_WA_lo + ((wm * 2 + 1) * 8 + kt) * 32 + lane);
        u64 bb[8];
        #pragma unroll
        for (int j = 0; j < 8; ++j)
            bb[j] = lds64(sb + OFF_B +
                          (uint32_t)((((wng * 8 + j) * 8 + kt) * 32 + lane) * 8));
        #pragma unroll
        for (int j = 0; j < 8; ++j) {
            mma16816(acc[0][j], a0h, bb[j]);
            mma16816(acc[0][j], a0l, bb[j]);
            mma16816(acc[1][j], a1h, bb[j]);
            mma16816(acc[1][j], a1l, bb[j]);
        }
    }

    // ---- epilogue: pre = acc + xi*u1[o] + xj*u2[o] + c[o]; out = silu(pre) ----
    // D frag: c0=(o,e) c1=(o,e+1) c2=(o+8,e) c3=(o+8,e+1),
    // o = wm*32 + i*16 + lane>>2, e = wng*64 + j*8 + (lane&3)*2
    float u1v[2][2], u2v[2][2], cv[2][2];
    #pragma unroll
    for (int i = 0; i < 2; ++i) {
        int ob = wm * 32 + i * 16 + (lane >> 2);
        u1v[i][0] = __ldg(g_u1 + ob);     u1v[i][1] = __ldg(g_u1 + ob + 8);
        u2v[i][0] = __ldg(g_u2 + ob);     u2v[i][1] = __ldg(g_u2 + ob + 8);
        cv[i][0]  = __ldg(g_c + ob);      cv[i][1]  = __ldg(g_c + ob + 8);
    }

    float* outb = out + ((size_t)b * NEDGE + e0) * HDIM;
    #pragma unroll
    for (int j = 0; j < 8; ++j) {
        const int eb = wng * 64 + j * 8 + (lane & 3) * 2;
        const float2 xiv = *(const float2*)(xi_s + eb);
        const float2 xjv = *(const float2*)(xj_s + eb);
        #pragma unroll
        for (int i = 0; i < 2; ++i) {
            const int ob = wm * 32 + i * 16 + (lane >> 2);
            #pragma unroll
            for (int h = 0; h < 2; ++h) {           // o vs o+8
                float p0 = acc[i][j][h * 2 + 0];
                float p1 = acc[i][j][h * 2 + 1];
                p0 = fmaf(xiv.x, u1v[i][h], p0);
                p0 = fmaf(xjv.x, u2v[i][h], p0) + cv[i][h];
                p1 = fmaf(xiv.y, u1v[i][h], p1);
                p1 = fmaf(xjv.y, u2v[i][h], p1) + cv[i][h];
                const int oo = ob + h * 8;
                outb[(size_t)eb * HDIM + oo]       = fast_silu(p0);
                outb[(size_t)(eb + 1) * HDIM + oo] = fast_silu(p1);
            }
        }
    }
}

// ---------------------------------------------------------------------------
extern "C" void kernel_launch(void* const* d_in, const int* in_sizes, int n_in,
                              void* d_out, int out_size) {
    const float* x     = (const float*)d_in[0];
    const float* rbf   = (const float*)d_in[1];
    const int*   iidx  = (const int*)d_in[2];   // int32 (JAX x64 disabled)
    const int*   jidx  = (const int*)d_in[3];
    const float* emb_w = (const float*)d_in[4];
    const float* emb_b = (const float*)d_in[5];
    const float* rbf_w = (const float*)d_in[6];
    const float* rbf_b = (const float*)d_in[7];
    const float* lin_w = (const float*)d_in[8];
    const float* lin_b = (const float*)d_in[9];
    float* out = (float*)d_out;

    precompute_all<<<64, 256>>>(emb_w, emb_b, lin_w, lin_b);

    cudaFuncSetAttribute(edge_mlp_kernel,
                         cudaFuncAttributeMaxDynamicSharedMemorySize, SMEM_BYTES);
    dim3 grid(NEDGE / TILE_E, BATCH);   // (512, 8)
    edge_mlp_kernel<<<grid, 256, SMEM_BYTES>>>(x, rbf, iidx, jidx, rbf_w, rbf_b, out);
}

// round 6
// speedup vs baseline: 3.5594x; 1.2560x over previous
#include <cuda_runtime.h>
#include <cuda_fp16.h>
#include <cstdint>

#define BATCH 8
#define NNODE 2048
#define NEDGE 65536
#define HDIM  128
#define NRAD  6
#define TILE_E 128

typedef unsigned long long u64;

// ---------------- device globals (no allocation) ----------------
__device__ float g_u1[HDIM];
__device__ float g_u2[HDIM];
__device__ float g_c[HDIM];
// W3 (lin_w[:,256:384]) as fp16 (single term), mma.m16n8k16 A-fragment order:
// index ((tm*8 + tk)*32 + lane) -> uint4 = {a0,a1,a2,a3}
__device__ uint4 g_WA[8 * 8 * 32];

// ---------------- smem byte offsets ----------------
#define OFF_B    0        // r fp16, B-fragment order: 32768 B
#define OFF_RBF  32768    // rbf tile [128][8] f32 (padded): 4096 B
#define OFF_XI   36864    // 512 B
#define OFF_XJ   37376    // 512 B
#define SMEM_BYTES 37888

// ---------------- helpers ----------------
__device__ __forceinline__ uint32_t smem_u32(const void* p) {
    uint32_t a;
    asm("{ .reg .u64 t; cvta.to.shared.u64 t, %1; cvt.u32.u64 %0, t; }" : "=r"(a) : "l"(p));
    return a;
}
__device__ __forceinline__ u64 lds64(uint32_t addr) {
    u64 v;
    asm volatile("ld.shared.b64 %0, [%1];" : "=l"(v) : "r"(addr));
    return v;
}
__device__ __forceinline__ void sts64(uint32_t addr, u64 v) {
    asm volatile("st.shared.b64 [%0], %1;" :: "r"(addr), "l"(v) : "memory");
}
// packed f16x2: low half <- lo, high half <- hi
__device__ __forceinline__ uint32_t cvt_f16x2(float lo, float hi) {
    uint32_t d;
    asm("cvt.rn.f16x2.f32 %0, %2, %1;" : "=r"(d) : "f"(lo), "f"(hi));
    return d;
}
__device__ __forceinline__ void mma16816(float* d, const uint4& a, u64 b) {
    uint32_t b0 = (uint32_t)b, b1 = (uint32_t)(b >> 32);
    asm volatile(
        "mma.sync.aligned.m16n8k16.row.col.f32.f16.f16.f32 "
        "{%0,%1,%2,%3}, {%4,%5,%6,%7}, {%8,%9}, {%0,%1,%2,%3};"
        : "+f"(d[0]), "+f"(d[1]), "+f"(d[2]), "+f"(d[3])
        : "r"(a.x), "r"(a.y), "r"(a.z), "r"(a.w), "r"(b0), "r"(b1));
}
// silu via single-MUFU tanh: z*sigmoid(z) = 0.5z + 0.5z*tanh(0.5z)
__device__ __forceinline__ float silu_t(float z) {
    float h = 0.5f * z;
    float t;
    asm("tanh.approx.f32 %0, %1;" : "=f"(t) : "f"(h));
    return fmaf(h, t, h);
}

// ---------------------------------------------------------------------------
// Single precompute kernel (2 launches/replay keeps ncu -s 5 on edge_mlp).
// grid=64, block=256.
//   part A: u1/u2/c for o = bid*2 + (tid>>7)
//   part B: blocks 0..7 pack W3 fp16 A-fragments (2048 threads)
// ---------------------------------------------------------------------------
__global__ void precompute_all(const float* __restrict__ emb_w,
                               const float* __restrict__ emb_b,
                               const float* __restrict__ lin_w,
                               const float* __restrict__ lin_b) {
    __shared__ float red[2][3][4];
    const int tid = threadIdx.x;
    const int bid = blockIdx.x;

    // ---- part A ----
    {
        const int half = tid >> 7;
        const int o = bid * 2 + half;
        const int h = tid & 127;
        float w1 = lin_w[o * (3 * HDIM) + h];
        float w2 = lin_w[o * (3 * HDIM) + HDIM + h];
        float u1 = w1 * emb_w[h];
        float u2 = w2 * emb_w[h];
        float cc = (w1 + w2) * emb_b[h];
        #pragma unroll
        for (int s = 16; s > 0; s >>= 1) {
            u1 += __shfl_down_sync(0xffffffff, u1, s);
            u2 += __shfl_down_sync(0xffffffff, u2, s);
            cc += __shfl_down_sync(0xffffffff, cc, s);
        }
        const int w4 = (tid >> 5) & 3;
        if ((tid & 31) == 0) {
            red[half][0][w4] = u1; red[half][1][w4] = u2; red[half][2][w4] = cc;
        }
        __syncthreads();
        if ((tid & 127) == 0) {
            g_u1[o] = red[half][0][0] + red[half][0][1] + red[half][0][2] + red[half][0][3];
            g_u2[o] = red[half][1][0] + red[half][1][1] + red[half][1][2] + red[half][1][3];
            g_c[o]  = red[half][2][0] + red[half][2][1] + red[half][2][2] + red[half][2][3]
                      + lin_b[o];
        }
    }

    // ---- part B: W3 fp16 A-fragment pack ----
    // A frag: a0=(o,k0|k1) a1=(o+8,k0|k1) a2=(o,k8|k9) a3=(o+8,k8|k9)
    // o = tm*16 + (lane>>2), k0 = tk*16 + (lane&3)*2.
    const int idx = bid * 256 + tid;
    if (idx < 2048) {
        const int lane = idx & 31;
        const int t    = idx >> 5;
        const int tk   = t & 7;
        const int tm   = t >> 3;
        const int o0 = tm * 16 + (lane >> 2);
        const int o1 = o0 + 8;
        const int k0 = tk * 16 + (lane & 3) * 2;

        const float* base = lin_w + 2 * HDIM;
        uint32_t a0 = cvt_f16x2(base[o0 * (3 * HDIM) + k0],     base[o0 * (3 * HDIM) + k0 + 1]);
        uint32_t a1 = cvt_f16x2(base[o1 * (3 * HDIM) + k0],     base[o1 * (3 * HDIM) + k0 + 1]);
        uint32_t a2 = cvt_f16x2(base[o0 * (3 * HDIM) + k0 + 8], base[o0 * (3 * HDIM) + k0 + 9]);
        uint32_t a3 = cvt_f16x2(base[o1 * (3 * HDIM) + k0 + 8], base[o1 * (3 * HDIM) + k0 + 9]);
        g_WA[idx] = make_uint4(a0, a1, a2, a3);
    }
}

// ---------------------------------------------------------------------------
// Main fused kernel: 1 CTA = 128 edges x 128 outputs, mma.sync fp16 1-term
// ---------------------------------------------------------------------------
__global__ void __launch_bounds__(256, 2)
edge_mlp_kernel(const float* __restrict__ x,
                const float* __restrict__ rbf,
                const int* __restrict__ iidx,
                const int* __restrict__ jidx,
                const float* __restrict__ rbf_w,
                const float* __restrict__ rbf_b,
                float* __restrict__ out) {
    extern __shared__ char sm[];
    const uint32_t sb = smem_u32(sm);

    const int b    = blockIdx.y;
    const int e0   = blockIdx.x * TILE_E;
    const int tid  = threadIdx.x;
    const int wid  = tid >> 5;
    const int lane = tid & 31;

    float* rbf_s = (float*)(sm + OFF_RBF);   // [128][8] padded
    float* xi_s  = (float*)(sm + OFF_XI);
    float* xj_s  = (float*)(sm + OFF_XJ);

    // ---- stage rbf tile into padded rows [e][8] ----
    {
        const float* src = rbf + ((size_t)b * NEDGE + e0) * NRAD;
        #pragma unroll
        for (int it = 0; it < 3; ++it) {
            int idx = tid + it * 256;        // 0..767
            int e = idx / NRAD, m = idx - e * NRAD;
            rbf_s[e * 8 + m] = src[idx];
        }
    }
    // ---- gather x_i / x_j (int32 indices; mask so bad index cannot fault) ----
    if (tid < 128) {
        int e = e0 + tid;
        int ii = iidx[e] & (NNODE - 1);
        int jj = jidx[e] & (NNODE - 1);
        xi_s[tid] = x[b * NNODE + ii];
        xj_s[tid] = x[b * NNODE + jj];
    }
    __syncthreads();

    // ---- r-phase: each lane owns 4 k-channels (kb,kb+1,kb+8,kb+9),
    //      weights hoisted to registers; iterate 16 edges; 1 STS.64/edge ----
    // B frag layout: addr = (((e>>3)*8 + kt)*32 + (e&7)*4 + q)*8,
    //   value = {r[e][kt*16+q*2], r[e][..+1], r[e][..+8], r[e][..+9]}
    {
        const int kt = lane >> 2;        // 0..7
        const int q  = lane & 3;         // 0..3
        const int kb = kt * 16 + q * 2;
        const int ks[4] = { kb, kb + 1, kb + 8, kb + 9 };

        float rw[4][NRAD], rb4[4];
        #pragma unroll
        for (int kk = 0; kk < 4; ++kk) {
            rb4[kk] = __ldg(rbf_b + ks[kk]);
            #pragma unroll
            for (int m = 0; m < NRAD; ++m)
                rw[kk][m] = __ldg(rbf_w + ks[kk] * NRAD + m);
        }

        const int ebase = wid * 16;
        #pragma unroll 2
        for (int t = 0; t < 16; ++t) {
            const int e = ebase + t;
            const float4 r03 = *(const float4*)(rbf_s + e * 8);
            const float2 r45 = *(const float2*)(rbf_s + e * 8 + 4);
            const float rv[NRAD] = { r03.x, r03.y, r03.z, r03.w, r45.x, r45.y };

            float z[4];
            #pragma unroll
            for (int kk = 0; kk < 4; ++kk) {
                z[kk] = rb4[kk];
                #pragma unroll
                for (int m = 0; m < NRAD; ++m)
                    z[kk] = fmaf(rv[m], rw[kk][m], z[kk]);
            }
            uint32_t b01 = cvt_f16x2(silu_t(z[0]), silu_t(z[1]));
            uint32_t b23 = cvt_f16x2(silu_t(z[2]), silu_t(z[3]));

            uint32_t off = (uint32_t)(((((e >> 3) * 8 + kt) * 32) + (e & 7) * 4 + q) * 8);
            sts64(sb + OFF_B + off, (u64)b01 | ((u64)b23 << 32));
        }
    }
    __syncthreads();

    // ---- mma: warp tile 32(o) x 64(e), single fp16 term ----
    const int wm  = wid & 3;    // o-group: rows wm*32..+31
    const int wng = wid >> 2;   // e-group: cols wng*64..+63

    float acc[2][8][4];
    #pragma unroll
    for (int i = 0; i < 2; ++i)
        #pragma unroll
        for (int j = 0; j < 8; ++j)
            #pragma unroll
            for (int q = 0; q < 4; ++q) acc[i][j][q] = 0.f;

    #pragma unroll
    for (int kt = 0; kt < 8; ++kt) {
        uint4 a0 = __ldg(g_WA + ((wm * 2 + 0) * 8 + kt) * 32 + lane);
        uint4 a1 = __ldg(g_WA + ((wm * 2 + 1) * 8 + kt) * 32 + lane);
        u64 bb[8];
        #pragma unroll
        for (int j = 0; j < 8; ++j)
            bb[j] = lds64(sb + OFF_B +
                          (uint32_t)((((wng * 8 + j) * 8 + kt) * 32 + lane) * 8));
        #pragma unroll
        for (int j = 0; j < 8; ++j) {
            mma16816(acc[0][j], a0, bb[j]);
            mma16816(acc[1][j], a1, bb[j]);
        }
    }

    // ---- epilogue: pre = acc + xi*u1[o] + xj*u2[o] + c[o]; out = silu(pre) ----
    // D frag: c0=(o,e) c1=(o,e+1) c2=(o+8,e) c3=(o+8,e+1),
    // o = wm*32 + i*16 + lane>>2, e = wng*64 + j*8 + (lane&3)*2
    float u1v[2][2], u2v[2][2], cv[2][2];
    #pragma unroll
    for (int i = 0; i < 2; ++i) {
        int ob = wm * 32 + i * 16 + (lane >> 2);
        u1v[i][0] = __ldg(g_u1 + ob);     u1v[i][1] = __ldg(g_u1 + ob + 8);
        u2v[i][0] = __ldg(g_u2 + ob);     u2v[i][1] = __ldg(g_u2 + ob + 8);
        cv[i][0]  = __ldg(g_c + ob);      cv[i][1]  = __ldg(g_c + ob + 8);
    }

    float* outb = out + ((size_t)b * NEDGE + e0) * HDIM;
    #pragma unroll
    for (int j = 0; j < 8; ++j) {
        const int eb = wng * 64 + j * 8 + (lane & 3) * 2;
        const float2 xiv = *(const float2*)(xi_s + eb);
        const float2 xjv = *(const float2*)(xj_s + eb);
        #pragma unroll
        for (int i = 0; i < 2; ++i) {
            const int ob = wm * 32 + i * 16 + (lane >> 2);
            #pragma unroll
            for (int h = 0; h < 2; ++h) {           // o vs o+8
                float p0 = acc[i][j][h * 2 + 0];
                float p1 = acc[i][j][h * 2 + 1];
                p0 = fmaf(xiv.x, u1v[i][h], p0);
                p0 = fmaf(xjv.x, u2v[i][h], p0) + cv[i][h];
                p1 = fmaf(xiv.y, u1v[i][h], p1);
                p1 = fmaf(xjv.y, u2v[i][h], p1) + cv[i][h];
                const int oo = ob + h * 8;
                outb[(size_t)eb * HDIM + oo]       = silu_t(p0);
                outb[(size_t)(eb + 1) * HDIM + oo] = silu_t(p1);
            }
        }
    }
}

// ---------------------------------------------------------------------------
extern "C" void kernel_launch(void* const* d_in, const int* in_sizes, int n_in,
                              void* d_out, int out_size) {
    const float* x     = (const float*)d_in[0];
    const float* rbf   = (const float*)d_in[1];
    const int*   iidx  = (const int*)d_in[2];   // int32 (JAX x64 disabled)
    const int*   jidx  = (const int*)d_in[3];
    const float* emb_w = (const float*)d_in[4];
    const float* emb_b = (const float*)d_in[5];
    const float* rbf_w = (const float*)d_in[6];
    const float* rbf_b = (const float*)d_in[7];
    const float* lin_w = (const float*)d_in[8];
    const float* lin_b = (const float*)d_in[9];
    float* out = (float*)d_out;

    precompute_all<<<64, 256>>>(emb_w, emb_b, lin_w, lin_b);

    cudaFuncSetAttribute(edge_mlp_kernel,
                         cudaFuncAttributeMaxDynamicSharedMemorySize, SMEM_BYTES);
    dim3 grid(NEDGE / TILE_E, BATCH);   // (512, 8)
    edge_mlp_kernel<<<grid, 256, SMEM_BYTES>>>(x, rbf, iidx, jidx, rbf_w, rbf_b, out);
}